// round 5
// baseline (speedup 1.0000x reference)
#include <cuda_runtime.h>
#include <math.h>

// Problem constants
#define BB   8
#define NN   4096
#define CC   768
#define HH   8
#define HD   96          // CC / HH
#define BN   32768       // BB * NN
#define C3   2304        // 3 * CC
#define BHCNT 64         // BB * HH

// Scratch (device globals: allocation-free, graph-capturable)
__device__ float g_qkv[(size_t)BN * C3];    // [bn][3C] row-major qkv
__device__ float g_ctx[(size_t)BN * CC];    // attention output, [bn][C] row-major
__device__ float g_gram[BHCNT * HD * HD];   // raw q.k^T per (b,h)
__device__ float g_attn[BHCNT * HD * HD];   // softmaxed attention
__device__ float g_qss[BHCNT * HD];         // sum q^2 over n, per (b,h,d)
__device__ float g_kss[BHCNT * HD];

// ---------------------------------------------------------------------------
// Zero the reduction scratch (atomicAdd targets)
// ---------------------------------------------------------------------------
__global__ void zero_kernel() {
    int i = blockIdx.x * 256 + threadIdx.x;
    if (i < BHCNT * HD * HD) g_gram[i] = 0.0f;
    if (i < BHCNT * HD) { g_qss[i] = 0.0f; g_kss[i] = 0.0f; }
}

// ---------------------------------------------------------------------------
// 128x128x8 register-blocked SGEMM (fp32).
// mode 0: C(g_qkv) = Aext(x) @ B(Wqkv)         M=32768, Nn=2304, K=768
// mode 1: Cext(out) = g_ctx @ B(Wproj) + bias  M=32768, Nn=768,  K=768
// ---------------------------------------------------------------------------
__global__ __launch_bounds__(256) void sgemm128(
    const float* __restrict__ Aext, const float* __restrict__ B,
    float* __restrict__ Cext, const float* __restrict__ bias,
    int Nn, int K, int mode)
{
    const float* A = (mode == 0) ? Aext : g_ctx;
    float* Cm      = (mode == 0) ? g_qkv : Cext;

    __shared__ float As[8][128];
    __shared__ float Bs[8][128];

    const int t  = threadIdx.x;
    const int tx = t & 15;
    const int ty = t >> 4;
    const int m0 = blockIdx.y * 128;
    const int n0 = blockIdx.x * 128;

    // global load mapping
    const int arow = t >> 1, acol = (t & 1) * 4;      // A: 128 rows x 8 cols
    const int brow = t >> 5, bcol = (t & 31) * 4;     // B: 8 rows x 128 cols
    const float* Aptr = A + (size_t)(m0 + arow) * K + acol;
    const float* Bptr = B + (size_t)brow * Nn + n0 + bcol;

    float acc[8][8];
#pragma unroll
    for (int i = 0; i < 8; i++)
#pragma unroll
        for (int j = 0; j < 8; j++) acc[i][j] = 0.0f;

    for (int k0 = 0; k0 < K; k0 += 8) {
        float4 av = *(const float4*)(Aptr + k0);
        float4 bv = *(const float4*)(Bptr + (size_t)k0 * Nn);
        As[acol + 0][arow] = av.x;
        As[acol + 1][arow] = av.y;
        As[acol + 2][arow] = av.z;
        As[acol + 3][arow] = av.w;
        *(float4*)&Bs[brow][bcol] = bv;
        __syncthreads();

#pragma unroll
        for (int kk = 0; kk < 8; kk++) {
            float a[8], b[8];
#pragma unroll
            for (int i = 0; i < 4; i++) {
                a[i]     = As[kk][ty * 4 + i];
                a[4 + i] = As[kk][64 + ty * 4 + i];
                b[i]     = Bs[kk][tx * 4 + i];
                b[4 + i] = Bs[kk][64 + tx * 4 + i];
            }
#pragma unroll
            for (int i = 0; i < 8; i++)
#pragma unroll
                for (int j = 0; j < 8; j++) acc[i][j] += a[i] * b[j];
        }
        __syncthreads();
    }

    float bb[8];
#pragma unroll
    for (int j = 0; j < 8; j++) bb[j] = 0.0f;
    if (bias != nullptr) {
#pragma unroll
        for (int j = 0; j < 4; j++) {
            bb[j]     = bias[n0 + tx * 4 + j];
            bb[4 + j] = bias[n0 + 64 + tx * 4 + j];
        }
    }

#pragma unroll
    for (int i = 0; i < 8; i++) {
        int r = (i < 4) ? (ty * 4 + i) : (64 + ty * 4 + (i - 4));
        float* crow = Cm + (size_t)(m0 + r) * Nn + n0;
        float4 v0 = make_float4(acc[i][0] + bb[0], acc[i][1] + bb[1],
                                acc[i][2] + bb[2], acc[i][3] + bb[3]);
        float4 v1 = make_float4(acc[i][4] + bb[4], acc[i][5] + bb[5],
                                acc[i][6] + bb[6], acc[i][7] + bb[7]);
        *(float4*)(crow + tx * 4) = v0;
        *(float4*)(crow + 64 + tx * 4) = v1;
    }
}

// ---------------------------------------------------------------------------
// Split-K Gram: per (b,h), G[d,e] += sum_n q[d,n]*k[e,n], plus sum-squares.
// grid (64, 8) : 8-way split over N for occupancy; atomicAdd reduction.
// ---------------------------------------------------------------------------
__global__ __launch_bounds__(256) void gram_kernel() {
    const int bh = blockIdx.x;
    const int s  = blockIdx.y;
    const int b  = bh >> 3, h = bh & 7;
    const int NSPLIT = NN / 8;       // 512 tokens per split
    const int nbase = s * NSPLIT;

    __shared__ float Qs[16][96];
    __shared__ float Ks[16][96];

    const int t  = threadIdx.x;
    const int tx = t & 15, ty = t >> 4;

    float acc[6][6];
#pragma unroll
    for (int i = 0; i < 6; i++)
#pragma unroll
        for (int j = 0; j < 6; j++) acc[i][j] = 0.0f;
    float nss = 0.0f;

    const float* qbase = g_qkv + (size_t)b * NN * C3 + h * HD;       // + n*C3 + d
    const float* kbase = qbase + CC;

    for (int n0 = nbase; n0 < nbase + NSPLIT; n0 += 16) {
        for (int i = t; i < 16 * 96; i += 256) {
            int nl = i / 96, d = i - nl * 96;
            size_t off = (size_t)(n0 + nl) * C3 + d;
            Qs[nl][d] = qbase[off];
            Ks[nl][d] = kbase[off];
        }
        __syncthreads();

        if (t < 192) {
            int d = (t < 96) ? t : (t - 96);
#pragma unroll
            for (int nl = 0; nl < 16; nl++) {
                float v = (t < 96) ? Qs[nl][d] : Ks[nl][d];
                nss += v * v;
            }
        }
#pragma unroll
        for (int nl = 0; nl < 16; nl++) {
            float a[6], c[6];
#pragma unroll
            for (int i = 0; i < 6; i++) {
                a[i] = Qs[nl][ty * 6 + i];
                c[i] = Ks[nl][tx * 6 + i];
            }
#pragma unroll
            for (int i = 0; i < 6; i++)
#pragma unroll
                for (int j = 0; j < 6; j++) acc[i][j] += a[i] * c[j];
        }
        __syncthreads();
    }

    float* G = g_gram + bh * HD * HD;
#pragma unroll
    for (int i = 0; i < 6; i++)
#pragma unroll
        for (int j = 0; j < 6; j++)
            atomicAdd(&G[(ty * 6 + i) * HD + tx * 6 + j], acc[i][j]);

    if (t < 96)       atomicAdd(&g_qss[bh * HD + t], nss);
    else if (t < 192) atomicAdd(&g_kss[bh * HD + (t - 96)], nss);
}

// ---------------------------------------------------------------------------
// Scale by 1/(||q|| ||k||) * temperature, then row-softmax. One thread/row.
// ---------------------------------------------------------------------------
__global__ void softmax_kernel(const float* __restrict__ temperature) {
    const int bh = blockIdx.x;
    const int h  = bh & 7;
    const int t  = threadIdx.x;

    __shared__ float invk[96];
    __shared__ float invq[96];
    if (t < 96) {
        invq[t] = 1.0f / fmaxf(sqrtf(g_qss[bh * HD + t]), 1e-12f);
        invk[t] = 1.0f / fmaxf(sqrtf(g_kss[bh * HD + t]), 1e-12f);
    }
    __syncthreads();

    if (t < 96) {
        const float tmp = temperature[h];
        const float* Grow = g_gram + bh * HD * HD + t * HD;
        float* Arow       = g_attn + bh * HD * HD + t * HD;
        const float sd = tmp * invq[t];

        float m = -1e30f;
        for (int e = 0; e < 96; e++) {
            float v = Grow[e] * sd * invk[e];
            m = fmaxf(m, v);
        }
        float sum = 0.0f;
        for (int e = 0; e < 96; e++) {
            float v = expf(Grow[e] * sd * invk[e] - m);
            Arow[e] = v;
            sum += v;
        }
        const float inv = 1.0f / sum;
        for (int e = 0; e < 96; e++) Arow[e] *= inv;
    }
}

// ---------------------------------------------------------------------------
// out[d,n] = sum_e attn[d,e] * v[e,n]; written straight into [B,N,C] layout.
// grid (64, 16): each block one (b,h) and a 256-token chunk.
// ---------------------------------------------------------------------------
__global__ __launch_bounds__(256) void av_kernel() {
    const int bh    = blockIdx.x;
    const int chunk = blockIdx.y;
    const int b = bh >> 3, h = bh & 7;

    __shared__ float At[96][97];
    __shared__ float Vs[16][97];

    const int t  = threadIdx.x;
    const int tx = t & 15, ty = t >> 4;

    for (int i = t; i < HD * HD; i += 256) {
        int d = i / 96, e = i - d * 96;
        At[d][e] = g_attn[bh * HD * HD + i];
    }

    const float* vbase = g_qkv + (size_t)b * NN * C3 + 2 * CC + h * HD;  // + n*C3 + e
    float* obase       = g_ctx + (size_t)b * NN * CC + h * HD;           // + n*CC + d

    const int nstart = chunk * 256;
    for (int n0 = nstart; n0 < nstart + 256; n0 += 16) {
        for (int i = t; i < 16 * 96; i += 256) {
            int nl = i / 96, e = i - nl * 96;
            Vs[nl][e] = vbase[(size_t)(n0 + nl) * C3 + e];
        }
        __syncthreads();

        float acc[6];
#pragma unroll
        for (int i = 0; i < 6; i++) acc[i] = 0.0f;
#pragma unroll
        for (int e = 0; e < 96; e++) {
            float v = Vs[tx][e];
#pragma unroll
            for (int i = 0; i < 6; i++) acc[i] += At[ty * 6 + i][e] * v;
        }
        float* orow = obase + (size_t)(n0 + tx) * CC + ty * 6;
#pragma unroll
        for (int i = 0; i < 6; i++) orow[i] = acc[i];
        __syncthreads();
    }
}

// ---------------------------------------------------------------------------
extern "C" void kernel_launch(void* const* d_in, const int* in_sizes, int n_in,
                              void* d_out, int out_size)
{
    const float* x     = (const float*)d_in[0];
    const float* Wqkv  = (const float*)d_in[1];
    const float* temp  = (const float*)d_in[2];
    const float* Wproj = (const float*)d_in[3];
    const float* bproj = (const float*)d_in[4];
    float* out = (float*)d_out;

    // 1) qkv = x @ Wqkv  -> g_qkv
    sgemm128<<<dim3(C3 / 128, BN / 128), 256>>>(x, Wqkv, nullptr, nullptr, C3, CC, 0);

    // 2) zero reduction scratch
    zero_kernel<<<(BHCNT * HD * HD + 255) / 256, 256>>>();

    // 3) raw Gram + norms (split-K, atomics)
    gram_kernel<<<dim3(BHCNT, 8), 256>>>();

    // 4) fold norms + temperature, softmax
    softmax_kernel<<<BHCNT, 128>>>(temp);

    // 5) attn @ v -> g_ctx in [B,N,C] layout
    av_kernel<<<dim3(BHCNT, 16), 256>>>();

    // 6) out = g_ctx @ Wproj + bproj
    sgemm128<<<dim3(CC / 128, BN / 128), 256>>>(nullptr, Wproj, out, bproj, CC, CC, 1);
}

// round 7
// speedup vs baseline: 1.8513x; 1.8513x over previous
#include <cuda_runtime.h>
#include <cuda_bf16.h>
#include <math.h>
#include <stdint.h>

// Problem constants
#define BB   8
#define NN   4096
#define CC   768
#define HH   8
#define HD   96
#define BN   32768
#define C3   2304
#define BHCNT 64

// ---------------------------------------------------------------------------
// Scratch (device globals: allocation-free, graph-capturable)
// ---------------------------------------------------------------------------
__device__ float g_qkv[(size_t)BN * C3];               // [bn][3C] fp32 qkv
__device__ __nv_bfloat16 g_xhi[(size_t)BN * CC];       // x split
__device__ __nv_bfloat16 g_xlo[(size_t)BN * CC];
__device__ __nv_bfloat16 g_chi[(size_t)BN * CC];       // ctx split (av output)
__device__ __nv_bfloat16 g_clo[(size_t)BN * CC];
__device__ __nv_bfloat16 g_wq_hi[(size_t)C3 * CC];     // Wqkv^T [2304][768]
__device__ __nv_bfloat16 g_wq_lo[(size_t)C3 * CC];
__device__ __nv_bfloat16 g_wp_hi[(size_t)CC * CC];     // Wproj^T [768][768]
__device__ __nv_bfloat16 g_wp_lo[(size_t)CC * CC];
__device__ float g_gram[BHCNT * HD * HD];
__device__ float g_attn[BHCNT * HD * HD];
__device__ float g_qss[BHCNT * HD];
__device__ float g_kss[BHCNT * HD];

// ---------------------------------------------------------------------------
// Baseline-PTX helpers (sm_80+, no 'a'-gated features)
// ---------------------------------------------------------------------------
__device__ __forceinline__ uint32_t smem_u32(const void* p) {
    uint32_t a;
    asm("{ .reg .u64 t; cvta.to.shared.u64 t, %1; cvt.u32.u64 %0, t; }" : "=r"(a) : "l"(p));
    return a;
}
__device__ __forceinline__ void cp16(uint32_t saddr, const void* g) {
    asm volatile("cp.async.cg.shared.global [%0], [%1], 16;" :: "r"(saddr), "l"(g) : "memory");
}
__device__ __forceinline__ void cp_commit() {
    asm volatile("cp.async.commit_group;" ::: "memory");
}
__device__ __forceinline__ void cp_wait0() {
    asm volatile("cp.async.wait_group 0;" ::: "memory");
}
__device__ __forceinline__ void ldsm4(uint32_t& r0, uint32_t& r1, uint32_t& r2, uint32_t& r3,
                                      uint32_t addr) {
    asm volatile("ldmatrix.sync.aligned.m8n8.x4.shared.b16 {%0,%1,%2,%3}, [%4];"
                 : "=r"(r0), "=r"(r1), "=r"(r2), "=r"(r3) : "r"(addr));
}
__device__ __forceinline__ void mma16816(float* d, const uint32_t* a, const uint32_t* b) {
    asm volatile(
        "mma.sync.aligned.m16n8k16.row.col.f32.bf16.bf16.f32 "
        "{%0,%1,%2,%3}, {%4,%5,%6,%7}, {%8,%9}, {%0,%1,%2,%3};"
        : "+f"(d[0]), "+f"(d[1]), "+f"(d[2]), "+f"(d[3])
        : "r"(a[0]), "r"(a[1]), "r"(a[2]), "r"(a[3]), "r"(b[0]), "r"(b[1]));
}

// ---------------------------------------------------------------------------
// bf16 hi/lo split conversion for x
// ---------------------------------------------------------------------------
__global__ void conv_x_kernel(const float* __restrict__ x) {
    size_t i = (size_t)blockIdx.x * 256 + threadIdx.x;
    const size_t total = (size_t)BN * CC / 4;
    for (; i < total; i += (size_t)gridDim.x * 256) {
        float4 v = ((const float4*)x)[i];
        __nv_bfloat16 h0 = __float2bfloat16(v.x), h1 = __float2bfloat16(v.y);
        __nv_bfloat16 h2 = __float2bfloat16(v.z), h3 = __float2bfloat16(v.w);
        __nv_bfloat16 l0 = __float2bfloat16(v.x - __bfloat162float(h0));
        __nv_bfloat16 l1 = __float2bfloat16(v.y - __bfloat162float(h1));
        __nv_bfloat16 l2 = __float2bfloat16(v.z - __bfloat162float(h2));
        __nv_bfloat16 l3 = __float2bfloat16(v.w - __bfloat162float(h3));
        g_xhi[i*4+0] = h0; g_xhi[i*4+1] = h1; g_xhi[i*4+2] = h2; g_xhi[i*4+3] = h3;
        g_xlo[i*4+0] = l0; g_xlo[i*4+1] = l1; g_xlo[i*4+2] = l2; g_xlo[i*4+3] = l3;
    }
}

// Transpose + split: out[n][k] = W[k][n], W is [K][Nn]
__global__ void transp_kernel(const float* __restrict__ W,
                              __nv_bfloat16* __restrict__ Thi,
                              __nv_bfloat16* __restrict__ Tlo,
                              int K, int Nn) {
    size_t i = (size_t)blockIdx.x * 256 + threadIdx.x;
    const size_t total = (size_t)K * Nn;
    for (; i < total; i += (size_t)gridDim.x * 256) {
        int n = (int)(i / K), k = (int)(i - (size_t)n * K);
        float v = W[(size_t)k * Nn + n];
        __nv_bfloat16 h = __float2bfloat16(v);
        Thi[i] = h;
        Tlo[i] = __float2bfloat16(v - __bfloat162float(h));
    }
}

// ---------------------------------------------------------------------------
// HMMA bf16-split GEMM: C[m][n] = sum_k A[m][k]*B[n][k]  (fp32-accurate)
// A = Ahi/Alo [M][768], B = Bhi/Blo [Nn][768], both row-major bf16, K-major.
// 3 passes folded into the chunk loop: hi*hi + hi*lo + lo*hi.
// CTA tile 128x128, 8 warps of 64x32; K-chunk 64; cp.async double buffer.
// SMEM: 2 stages x (A 16KB + B 16KB) = 64KB.
// ---------------------------------------------------------------------------
#define GEMM_SMEM_BYTES 65536
#define NCHUNK 36     // 12 k-chunks x 3 split passes

__global__ __launch_bounds__(256) void gemm_mma(
    const __nv_bfloat16* __restrict__ Ahi, const __nv_bfloat16* __restrict__ Alo,
    const __nv_bfloat16* __restrict__ Bhi, const __nv_bfloat16* __restrict__ Blo,
    float* __restrict__ C, const float* __restrict__ bias, int ldc)
{
    extern __shared__ char smem[];
    const uint32_t sb = smem_u32(smem);
    const int t = threadIdx.x;
    const int lane = t & 31, wid = t >> 5;
    const int m0 = blockIdx.y * 128;
    const int n0 = blockIdx.x * 128;
    const int wm = (wid & 1) * 64;       // warp m-offset
    const int wn = (wid >> 1) * 32;      // warp n-offset

    // --- loader precompute: 4 x 16B for A and for B per thread per chunk ---
    int lso[4], lgo[4];
#pragma unroll
    for (int i = 0; i < 4; i++) {
        int idx = t + 256 * i, row = idx >> 3, seg = idx & 7;
        lso[i] = row * 128 + ((seg * 16) ^ ((row & 7) << 4));  // swizzled smem off
        lgo[i] = row * CC + seg * 8;                           // gmem elem off
    }

    // --- compute precompute (ldmatrix lane addressing) ---
    const int q = lane >> 3, r = lane & 7;
    const uint32_t rx = (uint32_t)(r << 4);
    const int aro = r + (q & 1) * 8;      // A row-in-tile
    const int akb = (q >> 1) * 16;        // A k-half byte offset
    const int bro = r + (q >> 1) * 8;     // B row-in-tile
    const int bkb = (q & 1) * 16;         // B k-half byte offset
    uint32_t Ab[2][4], Bb[2][2];
#pragma unroll
    for (int s = 0; s < 2; s++) {
#pragma unroll
        for (int mt = 0; mt < 4; mt++)
            Ab[s][mt] = sb + s * 32768u + (uint32_t)(wm + mt * 16 + aro) * 128u;
#pragma unroll
        for (int n2 = 0; n2 < 2; n2++)
            Bb[s][n2] = sb + s * 32768u + 16384u + (uint32_t)(wn + n2 * 16 + bro) * 128u;
    }

    float acc[4][4][4];
#pragma unroll
    for (int mt = 0; mt < 4; mt++)
#pragma unroll
        for (int nt = 0; nt < 4; nt++)
#pragma unroll
            for (int i = 0; i < 4; i++) acc[mt][nt][i] = 0.0f;

    // --- preload chunk 0 (pass 0: hi*hi, k0 = 0) ---
#pragma unroll
    for (int i = 0; i < 4; i++) {
        cp16(sb + lso[i],          Ahi + (size_t)m0 * CC + lgo[i]);
        cp16(sb + 16384u + lso[i], Bhi + (size_t)n0 * CC + lgo[i]);
    }
    cp_commit();
    cp_wait0();
    __syncthreads();

    for (int c = 0; c < NCHUNK; c++) {
        const int s = c & 1;
        if (c + 1 < NCHUNK) {
            const int pn = c + 1;
            const int pass = pn / 12;
            const int k0 = (pn - pass * 12) * 64;
            const __nv_bfloat16* Ap = (pass == 2) ? Alo : Ahi;
            const __nv_bfloat16* Bp = (pass == 1) ? Blo : Bhi;
            const uint32_t st = sb + (uint32_t)((c + 1) & 1) * 32768u;
#pragma unroll
            for (int i = 0; i < 4; i++) {
                cp16(st + lso[i],          Ap + (size_t)m0 * CC + k0 + lgo[i]);
                cp16(st + 16384u + lso[i], Bp + (size_t)n0 * CC + k0 + lgo[i]);
            }
            cp_commit();
        }

        // compute on stage s: 4 k16 steps
#pragma unroll
        for (int kk = 0; kk < 4; kk++) {
            const uint32_t ak = ((uint32_t)(kk * 32 + akb)) ^ rx;
            const uint32_t bk = ((uint32_t)(kk * 32 + bkb)) ^ rx;
            uint32_t a[4][4];
#pragma unroll
            for (int mt = 0; mt < 4; mt++)
                ldsm4(a[mt][0], a[mt][1], a[mt][2], a[mt][3], Ab[s][mt] + ak);
            uint32_t bfr[4][2];
#pragma unroll
            for (int n2 = 0; n2 < 2; n2++) {
                uint32_t r0, r1, r2, r3;
                ldsm4(r0, r1, r2, r3, Bb[s][n2] + bk);
                bfr[n2 * 2][0] = r0;     bfr[n2 * 2][1] = r1;
                bfr[n2 * 2 + 1][0] = r2; bfr[n2 * 2 + 1][1] = r3;
            }
#pragma unroll
            for (int nt = 0; nt < 4; nt++)
#pragma unroll
                for (int mt = 0; mt < 4; mt++)
                    mma16816(acc[mt][nt], a[mt], bfr[nt]);
        }

        if (c + 1 < NCHUNK) {
            cp_wait0();
            __syncthreads();
        }
    }

    // --- epilogue: direct global stores of D fragments ---
    const int mrow = lane >> 2;
    const int ncol = (lane & 3) * 2;
#pragma unroll
    for (int nt = 0; nt < 4; nt++) {
        const int col = n0 + wn + nt * 8 + ncol;
        float b0 = 0.0f, b1 = 0.0f;
        if (bias != nullptr) { b0 = bias[col]; b1 = bias[col + 1]; }
#pragma unroll
        for (int mt = 0; mt < 4; mt++) {
            const int m = m0 + wm + mt * 16 + mrow;
            float2 v0 = make_float2(acc[mt][nt][0] + b0, acc[mt][nt][1] + b1);
            float2 v1 = make_float2(acc[mt][nt][2] + b0, acc[mt][nt][3] + b1);
            *(float2*)(C + (size_t)m * ldc + col) = v0;
            *(float2*)(C + (size_t)(m + 8) * ldc + col) = v1;
        }
    }
}

// ---------------------------------------------------------------------------
// Zero reduction scratch
// ---------------------------------------------------------------------------
__global__ void zero_kernel() {
    int i = blockIdx.x * 256 + threadIdx.x;
    if (i < BHCNT * HD * HD) g_gram[i] = 0.0f;
    if (i < BHCNT * HD) { g_qss[i] = 0.0f; g_kss[i] = 0.0f; }
}

// ---------------------------------------------------------------------------
// Split-K Gram + norms
// ---------------------------------------------------------------------------
__global__ __launch_bounds__(256) void gram_kernel() {
    const int bh = blockIdx.x;
    const int s  = blockIdx.y;
    const int b  = bh >> 3, h = bh & 7;
    const int NSPLIT = NN / 8;
    const int nbase = s * NSPLIT;

    __shared__ float Qs[16][96];
    __shared__ float Ks[16][96];

    const int t  = threadIdx.x;
    const int tx = t & 15, ty = t >> 4;

    float acc[6][6];
#pragma unroll
    for (int i = 0; i < 6; i++)
#pragma unroll
        for (int j = 0; j < 6; j++) acc[i][j] = 0.0f;
    float nss = 0.0f;

    const float* qbase = g_qkv + (size_t)b * NN * C3 + h * HD;
    const float* kbase = qbase + CC;

    for (int n0 = nbase; n0 < nbase + NSPLIT; n0 += 16) {
        for (int i = t; i < 16 * 96; i += 256) {
            int nl = i / 96, d = i - nl * 96;
            size_t off = (size_t)(n0 + nl) * C3 + d;
            Qs[nl][d] = qbase[off];
            Ks[nl][d] = kbase[off];
        }
        __syncthreads();

        if (t < 192) {
            int d = (t < 96) ? t : (t - 96);
#pragma unroll
            for (int nl = 0; nl < 16; nl++) {
                float v = (t < 96) ? Qs[nl][d] : Ks[nl][d];
                nss += v * v;
            }
        }
#pragma unroll
        for (int nl = 0; nl < 16; nl++) {
            float a[6], c[6];
#pragma unroll
            for (int i = 0; i < 6; i++) {
                a[i] = Qs[nl][ty * 6 + i];
                c[i] = Ks[nl][tx * 6 + i];
            }
#pragma unroll
            for (int i = 0; i < 6; i++)
#pragma unroll
                for (int j = 0; j < 6; j++) acc[i][j] += a[i] * c[j];
        }
        __syncthreads();
    }

    float* G = g_gram + bh * HD * HD;
#pragma unroll
    for (int i = 0; i < 6; i++)
#pragma unroll
        for (int j = 0; j < 6; j++)
            atomicAdd(&G[(ty * 6 + i) * HD + tx * 6 + j], acc[i][j]);

    if (t < 96)       atomicAdd(&g_qss[bh * HD + t], nss);
    else if (t < 192) atomicAdd(&g_kss[bh * HD + (t - 96)], nss);
}

// ---------------------------------------------------------------------------
// Softmax with folded norms + temperature
// ---------------------------------------------------------------------------
__global__ void softmax_kernel(const float* __restrict__ temperature) {
    const int bh = blockIdx.x;
    const int h  = bh & 7;
    const int t  = threadIdx.x;

    __shared__ float invk[96];
    __shared__ float invq[96];
    if (t < 96) {
        invq[t] = 1.0f / fmaxf(sqrtf(g_qss[bh * HD + t]), 1e-12f);
        invk[t] = 1.0f / fmaxf(sqrtf(g_kss[bh * HD + t]), 1e-12f);
    }
    __syncthreads();

    if (t < 96) {
        const float tmp = temperature[h];
        const float* Grow = g_gram + bh * HD * HD + t * HD;
        float* Arow       = g_attn + bh * HD * HD + t * HD;
        const float sd = tmp * invq[t];

        float m = -1e30f;
        for (int e = 0; e < 96; e++) {
            float v = Grow[e] * sd * invk[e];
            m = fmaxf(m, v);
        }
        float sum = 0.0f;
        for (int e = 0; e < 96; e++) {
            float v = expf(Grow[e] * sd * invk[e] - m);
            Arow[e] = v;
            sum += v;
        }
        const float inv = 1.0f / sum;
        for (int e = 0; e < 96; e++) Arow[e] *= inv;
    }
}

// ---------------------------------------------------------------------------
// attn @ v -> ctx, written directly as bf16 hi/lo split in [B,N,C] layout
// ---------------------------------------------------------------------------
__global__ __launch_bounds__(256) void av_kernel() {
    const int bh    = blockIdx.x;
    const int chunk = blockIdx.y;
    const int b = bh >> 3, h = bh & 7;

    __shared__ float At[96][97];
    __shared__ float Vs[16][97];

    const int t  = threadIdx.x;
    const int tx = t & 15, ty = t >> 4;

    for (int i = t; i < HD * HD; i += 256) {
        int d = i / 96, e = i - d * 96;
        At[d][e] = g_attn[bh * HD * HD + i];
    }

    const float* vbase = g_qkv + (size_t)b * NN * C3 + 2 * CC + h * HD;
    __nv_bfloat16* ohbase = g_chi + (size_t)b * NN * CC + h * HD;
    __nv_bfloat16* olbase = g_clo + (size_t)b * NN * CC + h * HD;

    const int nstart = chunk * 256;
    for (int n0 = nstart; n0 < nstart + 256; n0 += 16) {
        for (int i = t; i < 16 * 96; i += 256) {
            int nl = i / 96, e = i - nl * 96;
            Vs[nl][e] = vbase[(size_t)(n0 + nl) * C3 + e];
        }
        __syncthreads();

        float acc[6];
#pragma unroll
        for (int i = 0; i < 6; i++) acc[i] = 0.0f;
#pragma unroll
        for (int e = 0; e < 96; e++) {
            float v = Vs[tx][e];
#pragma unroll
            for (int i = 0; i < 6; i++) acc[i] += At[ty * 6 + i][e] * v;
        }
        size_t ooff = (size_t)(n0 + tx) * CC + ty * 6;
#pragma unroll
        for (int i = 0; i < 6; i++) {
            __nv_bfloat16 hh = __float2bfloat16(acc[i]);
            ohbase[ooff + i] = hh;
            olbase[ooff + i] = __float2bfloat16(acc[i] - __bfloat162float(hh));
        }
        __syncthreads();
    }
}

// ---------------------------------------------------------------------------
extern "C" void kernel_launch(void* const* d_in, const int* in_sizes, int n_in,
                              void* d_out, int out_size)
{
    const float* x     = (const float*)d_in[0];
    const float* Wqkv  = (const float*)d_in[1];
    const float* temp  = (const float*)d_in[2];
    const float* Wproj = (const float*)d_in[3];
    const float* bproj = (const float*)d_in[4];
    float* out = (float*)d_out;

    cudaFuncSetAttribute(gemm_mma, cudaFuncAttributeMaxDynamicSharedMemorySize,
                         GEMM_SMEM_BYTES);

    __nv_bfloat16 *xhi, *xlo, *chi, *clo, *wqh, *wql, *wph, *wpl;
    cudaGetSymbolAddress((void**)&xhi, g_xhi);
    cudaGetSymbolAddress((void**)&xlo, g_xlo);
    cudaGetSymbolAddress((void**)&chi, g_chi);
    cudaGetSymbolAddress((void**)&clo, g_clo);
    cudaGetSymbolAddress((void**)&wqh, g_wq_hi);
    cudaGetSymbolAddress((void**)&wql, g_wq_lo);
    cudaGetSymbolAddress((void**)&wph, g_wp_hi);
    cudaGetSymbolAddress((void**)&wpl, g_wp_lo);
    float* qkv;
    cudaGetSymbolAddress((void**)&qkv, g_qkv);

    // 1) split conversions
    conv_x_kernel<<<1184, 256>>>(x);
    transp_kernel<<<1184, 256>>>(Wqkv, wqh, wql, CC, C3);
    transp_kernel<<<592, 256>>>(Wproj, wph, wpl, CC, CC);

    // 2) qkv = x @ Wqkv via HMMA (bf16-split, 3-pass)
    gemm_mma<<<dim3(C3 / 128, BN / 128), 256, GEMM_SMEM_BYTES>>>(
        xhi, xlo, wqh, wql, qkv, nullptr, C3);

    // 3) attention middle
    zero_kernel<<<(BHCNT * HD * HD + 255) / 256, 256>>>();
    gram_kernel<<<dim3(BHCNT, 8), 256>>>();
    softmax_kernel<<<BHCNT, 128>>>(temp);
    av_kernel<<<dim3(BHCNT, 16), 256>>>();

    // 4) out = ctx @ Wproj + bias via HMMA (bf16-split, 3-pass)
    gemm_mma<<<dim3(CC / 128, BN / 128), 256, GEMM_SMEM_BYTES>>>(
        chi, clo, wph, wpl, out, bproj, CC);
}